// round 16
// baseline (speedup 1.0000x reference)
#include <cuda_runtime.h>
#include <cstdint>

#define NNODES 64
#define NEDGES 128
#define NGRAPH 4

typedef unsigned long long ull;

#define O1 2000
#define O2 500
#define O3 100
#define K2 2000
#define K3 500
#define S2 150      // layer-2 K slices (kChunk 80, 150*80 = 12000 exact)
#define S3 94       // layer-3 K slices (kChunk 32)

// ---------------- scratch ----------------
__device__ float g_A2T[6 * K2 * 64];          // 3 MB
__device__ float g_A3T[6 * K3 * 64];
__device__ float g_Z2p[S2 * 64 * O2];         // 19.2 MB per-slice partials
__device__ float g_Z3p[S3 * 64 * O3];
__device__ float g_H1 [64 * K2];
__device__ float g_H2 [64 * K3];
__device__ float g_H3 [64 * O3];

// ---------------- helpers ----------------
__device__ __forceinline__ void gdc_wait() {
    asm volatile("griddepcontrol.wait;" ::: "memory");
}
__device__ __forceinline__ void gdc_launch() {
    asm volatile("griddepcontrol.launch_dependents;" ::: "memory");
}
__device__ __forceinline__ ull dup2(float x) {
    ull r; asm("mov.b64 %0, {%1, %1};" : "=l"(r) : "f"(x)); return r;
}
__device__ __forceinline__ void fma2(ull &d, ull a, ull b) {
    asm("fma.rn.f32x2 %0, %1, %2, %3;" : "=l"(d) : "l"(a), "l"(b), "l"(d));
}
__device__ __forceinline__ float2 unpk(ull v) {
    float2 r; asm("mov.b64 {%0, %1}, %2;" : "=f"(r.x), "=f"(r.y) : "l"(v)); return r;
}
__device__ __forceinline__ void cpa16(void* dst, const void* src) {
    uint32_t d = (uint32_t)__cvta_generic_to_shared(dst);
    asm volatile("cp.async.cg.shared.global [%0], [%1], 16;\n" :: "r"(d), "l"(src));
}
__device__ __forceinline__ void cpa_commit() {
    asm volatile("cp.async.commit_group;\n" ::: "memory");
}
template<int N> __device__ __forceinline__ void cpa_wait() {
    asm volatile("cp.async.wait_group %0;\n" :: "n"(N) : "memory");
}

#define FMA_BLOCK \
    ull b0 = dup2(bL.x), b1 = dup2(bL.y), b2 = dup2(bL.z), b3 = dup2(bL.w); \
    ull b4 = dup2(bH.x), b5 = dup2(bH.y), b6 = dup2(bH.z), b7 = dup2(bH.w); \
    fma2(acc[0][0], a0, b0); fma2(acc[0][1], a0, b1); fma2(acc[0][2], a0, b2); fma2(acc[0][3], a0, b3); \
    fma2(acc[0][4], a0, b4); fma2(acc[0][5], a0, b5); fma2(acc[0][6], a0, b6); fma2(acc[0][7], a0, b7); \
    fma2(acc[1][0], a1, b0); fma2(acc[1][1], a1, b1); fma2(acc[1][2], a1, b2); fma2(acc[1][3], a1, b3); \
    fma2(acc[1][4], a1, b4); fma2(acc[1][5], a1, b5); fma2(acc[1][6], a1, b6); fma2(acc[1][7], a1, b7); \
    fma2(acc[2][0], a2, b0); fma2(acc[2][1], a2, b1); fma2(acc[2][2], a2, b2); fma2(acc[2][3], a2, b3); \
    fma2(acc[2][4], a2, b4); fma2(acc[2][5], a2, b5); fma2(acc[2][6], a2, b6); fma2(acc[2][7], a2, b7); \
    fma2(acc[3][0], a3, b0); fma2(acc[3][1], a3, b1); fma2(acc[3][2], a3, b2); fma2(acc[3][3], a3, b3); \
    fma2(acc[3][4], a3, b4); fma2(acc[3][5], a3, b5); fma2(acc[3][6], a3, b6); fma2(acc[3][7], a3, b7);

// ================= k_main1: layer-1 GEMM + FUSED bias/relu -> H1 + A2T identity rows =================
__global__ __launch_bounds__(128) void k_main1(
    const float* __restrict__ x, const int* __restrict__ eidx,
    const float* __restrict__ eattr,
    const float* __restrict__ We, const float* __restrict__ be,
    const float* __restrict__ root, const float* __restrict__ bias,
    float* __restrict__ H, float* __restrict__ A2T)
{
    __shared__ float sA[54 * 64];
    __shared__ float sB[54 * 128];

    gdc_wait();
    gdc_launch();
    const int t = threadIdx.x;
    const int c0 = blockIdx.x * 128;

    for (int i = t; i < 54 * 32; i += 128) {
        int r = i >> 5, c4 = (i & 31) * 4;
        int c = c0 + c4;
        float4* bd = (float4*)&sB[r * 128 + c4];
        if (c < O1) {
            const float* P;
            if      (r < 36) P = We   + (size_t)r * O1;
            else if (r < 45) P = be   + (size_t)(r - 36) * O1;
            else             P = root + (size_t)(r - 45) * O1;
            cpa16(bd, P + c);
        } else *bd = make_float4(0,0,0,0);
    }
    cpa_commit();

    for (int i = t; i < 54 * 64; i += 128) sA[i] = 0.f;
    __syncthreads();
    if (t < NEDGES) {
        int s = eidx[t], d = eidx[NEDGES + t];
        float xs[9];
        #pragma unroll
        for (int i = 0; i < 9; i++) xs[i] = x[s * 9 + i];
        #pragma unroll
        for (int j = 0; j < 4; j++) {
            float w = eattr[t * 4 + j];
            #pragma unroll
            for (int i = 0; i < 9; i++)
                atomicAdd(&sA[(j * 9 + i) * 64 + d], w * xs[i]);
        }
        #pragma unroll
        for (int i = 0; i < 9; i++)
            atomicAdd(&sA[(36 + i) * 64 + d], xs[i]);
    }
    if (t < 64) {
        #pragma unroll
        for (int i = 0; i < 9; i++)
            sA[(45 + i) * 64 + t] = x[t * 9 + i];
    }
    cpa_wait<0>();
    __syncthreads();

    const int tx = t & 15, ty = t >> 4;
    ull acc[4][8];
    #pragma unroll
    for (int r = 0; r < 4; r++)
        #pragma unroll
        for (int j = 0; j < 8; j++) acc[r][j] = 0ull;

    for (int r = 0; r < 54; r++) {
        const float* as = &sA[r * 64 + 8 * ty];
        ull a0 = *(const ull*)(as);
        ull a1 = *(const ull*)(as + 2);
        ull a2 = *(const ull*)(as + 4);
        ull a3 = *(const ull*)(as + 6);
        float4 bL = *(const float4*)&sB[r * 128 + 4 * tx];
        float4 bH = *(const float4*)&sB[r * 128 + 64 + 4 * tx];
        FMA_BLOCK
    }

    // ---- fused epilogue: +bias, relu, write H (row-major) + A2T identity (column-major) ----
    const int cL = c0 + 4 * tx;           // always < O1 (max 1983)
    const int cH = c0 + 64 + 4 * tx;      // may exceed
    const bool hv = (cH + 3 < O1);
    float4 bL4 = *(const float4*)&bias[cL];
    float4 bH4 = hv ? *(const float4*)&bias[cH] : make_float4(0,0,0,0);

    float rr[8][8];                       // [local row][col: 0..3 = L, 4..7 = H]
    #pragma unroll
    for (int rp = 0; rp < 4; rp++) {
        #pragma unroll
        for (int jc = 0; jc < 4; jc++) {
            float2 vL = unpk(acc[rp][jc]);
            float2 vH = unpk(acc[rp][4 + jc]);
            float bl = (&bL4.x)[jc], bh = (&bH4.x)[jc];
            rr[2 * rp][jc]         = fmaxf(vL.x + bl, 0.f);
            rr[2 * rp + 1][jc]     = fmaxf(vL.y + bl, 0.f);
            rr[2 * rp][4 + jc]     = fmaxf(vH.x + bh, 0.f);
            rr[2 * rp + 1][4 + jc] = fmaxf(vH.y + bh, 0.f);
        }
    }
    // H rows (O1 == K2 == 2000)
    #pragma unroll
    for (int lr = 0; lr < 8; lr++) {
        int m = 8 * ty + lr;
        *(float4*)&H[(size_t)m * K2 + cL] = make_float4(rr[lr][0], rr[lr][1], rr[lr][2], rr[lr][3]);
        if (hv)
            *(float4*)&H[(size_t)m * K2 + cH] = make_float4(rr[lr][4], rr[lr][5], rr[lr][6], rr[lr][7]);
    }
    // A2T identity rows: A2T[(5*K2 + k)*64 + m], m = 8ty..8ty+7 contiguous
    #pragma unroll
    for (int jc = 0; jc < 4; jc++) {
        {
            int k = cL + jc;
            float* dst = A2T + (size_t)(5 * K2 + k) * 64 + 8 * ty;
            *(float4*)dst       = make_float4(rr[0][jc], rr[1][jc], rr[2][jc], rr[3][jc]);
            *(float4*)(dst + 4) = make_float4(rr[4][jc], rr[5][jc], rr[6][jc], rr[7][jc]);
        }
        if (hv) {
            int k = cH + jc;
            float* dst = A2T + (size_t)(5 * K2 + k) * 64 + 8 * ty;
            *(float4*)dst       = make_float4(rr[0][4+jc], rr[1][4+jc], rr[2][4+jc], rr[3][4+jc]);
            *(float4*)(dst + 4) = make_float4(rr[4][4+jc], rr[5][4+jc], rr[6][4+jc], rr[7][4+jc]);
        }
    }
}

// ================= k_relu<G>: h = relu(sum_g Zp + b); H dense + identity A'' rows =================
// grid (ceil(Klen/64), 8): 8 node-rows per block, full-MLP partial sum.
template<int G>
__global__ __launch_bounds__(128) void k_relu(
    const float* __restrict__ Z, const float* __restrict__ bias, int Klen,
    float* __restrict__ AoutT, float* __restrict__ Hout)
{
    __shared__ float sh[8][68];

    gdc_wait();
    gdc_launch();

    const int t  = threadIdx.x;
    const int k0 = blockIdx.x * 64;
    const int n0 = blockIdx.y * 8;

    {
        const int nl = t >> 4;
        const int n  = n0 + nl;
        const int k4 = (t & 15) << 2;
        const int kk = k0 + k4;
        float4 v = make_float4(0.f, 0.f, 0.f, 0.f);
        if (kk < Klen) {
            v = *(const float4*)&bias[kk];
            #pragma unroll
            for (int g0 = 0; g0 < G; g0 += 8) {
                float4 p[8];
                #pragma unroll
                for (int g = 0; g < 8; g++)
                    if (g0 + g < G)
                        p[g] = *(const float4*)&Z[(size_t)(g0 + g) * 64 * Klen
                                                  + (size_t)n * Klen + kk];
                #pragma unroll
                for (int g = 0; g < 8; g++)
                    if (g0 + g < G) {
                        v.x += p[g].x; v.y += p[g].y; v.z += p[g].z; v.w += p[g].w;
                    }
            }
            v.x = fmaxf(v.x, 0.f); v.y = fmaxf(v.y, 0.f);
            v.z = fmaxf(v.z, 0.f); v.w = fmaxf(v.w, 0.f);
            *(float4*)&Hout[(size_t)n * Klen + kk] = v;
        }
        *(float4*)&sh[nl][k4] = v;
    }
    __syncthreads();

    if (t < 64) {
        const int kk = k0 + t;
        if (kk < Klen) {
            float* dst = AoutT + (size_t)(5 * (size_t)Klen + kk) * 64 + n0;
            float4 a = make_float4(sh[0][t], sh[1][t], sh[2][t], sh[3][t]);
            float4 b = make_float4(sh[4][t], sh[5][t], sh[6][t], sh[7][t]);
            *(float4*)dst       = a;
            *(float4*)(dst + 4) = b;
        }
    }
}

// ================= k_pgemm: M_j rows of A'' = P_j^T H =================
__global__ __launch_bounds__(256) void k_pgemm(
    const float* __restrict__ H, int Klen,
    const int* __restrict__ eidx, const float* __restrict__ eattr,
    float* __restrict__ AoutT)
{
    __shared__ float sh[64 * 128];
    __shared__ float sP[64 * 64];

    gdc_wait();
    gdc_launch();

    const int t  = threadIdx.x;
    const int k0 = blockIdx.x * 128;
    const int j  = blockIdx.y;

    for (int i = t; i < 2048; i += 256) {
        int n = i >> 5, k4 = (i & 31) << 2;
        int kk = k0 + k4;
        if (kk < Klen) cpa16(&sh[n * 128 + k4], &H[(size_t)n * Klen + kk]);
        else           *(float4*)&sh[n * 128 + k4] = make_float4(0,0,0,0);
    }
    cpa_commit();
    for (int i = t; i < 4096; i += 256) sP[i] = 0.f;
    __syncthreads();
    if (t < NEDGES) {
        int s = eidx[t], d = eidx[NEDGES + t];
        float w = (j < 4) ? eattr[t * 4 + j] : 1.f;
        atomicAdd(&sP[s * 64 + d], w);
    }
    cpa_wait<0>();
    __syncthreads();

    const int tx = t & 31;
    const int ty = t >> 5;
    ull acc[4][4];
    #pragma unroll
    for (int r = 0; r < 4; r++)
        #pragma unroll
        for (int c = 0; c < 4; c++) acc[r][c] = 0ull;

    for (int n = 0; n < 64; n++) {
        const float* as = &sP[n * 64 + 8 * ty];
        ull a0 = *(const ull*)(as);
        ull a1 = *(const ull*)(as + 2);
        ull a2 = *(const ull*)(as + 4);
        ull a3 = *(const ull*)(as + 6);
        float4 b = *(const float4*)&sh[n * 128 + 4 * tx];
        ull b0 = dup2(b.x), b1 = dup2(b.y), b2 = dup2(b.z), b3 = dup2(b.w);
        fma2(acc[0][0], a0, b0); fma2(acc[0][1], a0, b1); fma2(acc[0][2], a0, b2); fma2(acc[0][3], a0, b3);
        fma2(acc[1][0], a1, b0); fma2(acc[1][1], a1, b1); fma2(acc[1][2], a1, b2); fma2(acc[1][3], a1, b3);
        fma2(acc[2][0], a2, b0); fma2(acc[2][1], a2, b1); fma2(acc[2][2], a2, b2); fma2(acc[2][3], a2, b3);
        fma2(acc[3][0], a3, b0); fma2(acc[3][1], a3, b1); fma2(acc[3][2], a3, b2); fma2(acc[3][3], a3, b3);
    }

    #pragma unroll
    for (int jc = 0; jc < 4; jc++) {
        int k = k0 + 4 * tx + jc;
        if (k < Klen) {
            size_t row = (size_t)((size_t)j * Klen + k) * 64;
            float2 p0 = unpk(acc[0][jc]), p1 = unpk(acc[1][jc]);
            float2 p2 = unpk(acc[2][jc]), p3 = unpk(acc[3][jc]);
            *(float4*)&AoutT[row + 8 * ty]     = make_float4(p0.x, p0.y, p1.x, p1.y);
            *(float4*)&AoutT[row + 8 * ty + 4] = make_float4(p2.x, p2.y, p3.x, p3.y);
        }
    }
}

// ================= k_main: split-K GEMM, plain per-slice store epilogue =================
__global__ __launch_bounds__(128) void k_main(
    const float* __restrict__ AT, int Kj, int O,
    const float* __restrict__ We, const float* __restrict__ be,
    const float* __restrict__ root, float* __restrict__ Zp, int kChunk)
{
    __shared__ float As[3][16][68];
    __shared__ float Bs[3][16][128];

    gdc_wait();
    gdc_launch();

    const int t    = threadIdx.x;
    const int Ktot = 6 * Kj;
    const int c0   = blockIdx.x * 128;
    const int k0   = blockIdx.y * kChunk;
    const int kend = min(k0 + kChunk, Ktot);
    const int nsteps = (kend - k0 + 15) >> 4;
    float* Z = Zp + (size_t)blockIdx.y * 64 * O;

    const int kkB   = t >> 3;
    const int cbase = (t & 7) * 16;
    const float4 z4 = make_float4(0.f, 0.f, 0.f, 0.f);

    auto stage = [&](int s, int buf) {
        const int kt = k0 + s * 16;
        const int kb = kend - kt;
        #pragma unroll
        for (int i = 0; i < 4; i++) {
            int cl = cbase + 4 * i;
            int c  = c0 + cl;
            float4* bd = (float4*)&Bs[buf][kkB][cl];
            if (kkB < kb && c < O) {
                int rr = kt + kkB;
                const float* P;
                if      (rr < 4 * Kj) P = We   + (size_t)rr * O;
                else if (rr < 5 * Kj) P = be   + (size_t)(rr - 4 * Kj) * O;
                else                  P = root + (size_t)(rr - 5 * Kj) * O;
                cpa16(bd, P + c);
            } else *bd = z4;
        }
        #pragma unroll
        for (int i = 0; i < 2; i++) {
            int q  = t + 128 * i;
            int kk = q >> 4, m4 = (q & 15) * 4;
            float4* ad = (float4*)&As[buf][kk][m4];
            if (kk < kb) cpa16(ad, AT + (size_t)(kt + kk) * 64 + m4);
            else         *ad = z4;
        }
        cpa_commit();
    };

    stage(0, 0);
    if (nsteps > 1) stage(1, 1);

    const int tx = t & 15, ty = t >> 4;
    ull acc[4][8];
    #pragma unroll
    for (int r = 0; r < 4; r++)
        #pragma unroll
        for (int j = 0; j < 8; j++) acc[r][j] = 0ull;

    for (int s = 0; s < nsteps; s++) {
        const int buf = s % 3;
        if (s + 2 < nsteps)      { stage(s + 2, (s + 2) % 3); cpa_wait<2>(); }
        else if (s + 1 < nsteps) { cpa_wait<1>(); }
        else                     { cpa_wait<0>(); }
        __syncthreads();

        #pragma unroll
        for (int kk = 0; kk < 16; kk++) {
            const float* as = &As[buf][kk][8 * ty];
            ull a0 = *(const ull*)(as);
            ull a1 = *(const ull*)(as + 2);
            ull a2 = *(const ull*)(as + 4);
            ull a3 = *(const ull*)(as + 6);
            float4 bL = *(const float4*)&Bs[buf][kk][4 * tx];
            float4 bH = *(const float4*)&Bs[buf][kk][64 + 4 * tx];
            FMA_BLOCK
        }
        __syncthreads();
    }

    const int cL = c0 + 4 * tx;
    const int cH = c0 + 64 + 4 * tx;
    #pragma unroll
    for (int rp = 0; rp < 4; rp++) {
        int m = 8 * ty + 2 * rp;
        float2 v[8];
        #pragma unroll
        for (int j = 0; j < 8; j++) v[j] = unpk(acc[rp][j]);
        if (cL < O) {
            *(float4*)&Z[(size_t)m       * O + cL] = make_float4(v[0].x, v[1].x, v[2].x, v[3].x);
            *(float4*)&Z[(size_t)(m + 1) * O + cL] = make_float4(v[0].y, v[1].y, v[2].y, v[3].y);
        }
        if (cH + 3 < O) {
            *(float4*)&Z[(size_t)m       * O + cH] = make_float4(v[4].x, v[5].x, v[6].x, v[7].x);
            *(float4*)&Z[(size_t)(m + 1) * O + cH] = make_float4(v[4].y, v[5].y, v[6].y, v[7].y);
        }
    }
}

// ================= fused FCN head (reads dense relu'd H3) =================
__global__ __launch_bounds__(256) void k_head(
    const float* __restrict__ H3, const int* __restrict__ batch,
    const float* __restrict__ W1, const float* __restrict__ c1,
    const float* __restrict__ W2, const float* __restrict__ c2,
    const float* __restrict__ W3, const float* __restrict__ c3,
    const float* __restrict__ W4, const float* __restrict__ c4,
    float* __restrict__ out)
{
    __shared__ float gS[100];
    __shared__ float s1[1000];
    __shared__ float part[200];
    __shared__ float s2[100];
    __shared__ float s3[50];
    __shared__ int   sb[NNODES];

    gdc_wait();

    const int g = blockIdx.x;
    const int t = threadIdx.x;

    if (t < NNODES) sb[t] = batch[t];
    __syncthreads();

    if (t < 100) {
        float a = 0.f;
        for (int n = 0; n < NNODES; n++)
            if (sb[n] == g) a += H3[n * 100 + t];
        gS[t] = a;
    }
    __syncthreads();

    for (int f = t; f < 1000; f += 256) {
        float a = c1[f];
        for (int kq = 0; kq < 100; kq++) a += gS[kq] * W1[kq * 1000 + f];
        s1[f] = fmaxf(a, 0.f);
    }
    __syncthreads();

    if (t < 200) {
        int f = t % 100, hh = t / 100;
        float a = 0.f;
        int kq0 = hh * 500;
        for (int kq = kq0; kq < kq0 + 500; kq++) a += s1[kq] * W2[kq * 100 + f];
        part[t] = a;
    }
    __syncthreads();
    if (t < 100) s2[t] = fmaxf(part[t] + part[100 + t] + c2[t], 0.f);
    __syncthreads();

    if (t < 50) {
        float a = c3[t];
        for (int kq = 0; kq < 100; kq++) a += s2[kq] * W3[kq * 50 + t];
        s3[t] = fmaxf(a, 0.f);
    }
    __syncthreads();

    if (t < 32) {
        float a = (t < 50) ? s3[t] * W4[t] : 0.f;
        if (t + 32 < 50) a += s3[t + 32] * W4[t + 32];
        #pragma unroll
        for (int o = 16; o > 0; o >>= 1)
            a += __shfl_xor_sync(0xffffffffu, a, o);
        if (t == 0) out[g] = a + c4[0];
    }
}

// ---------------- launch (8 PDL-chained kernels, no global atomics) ----------------
extern "C" void kernel_launch(void* const* d_in, const int* in_sizes, int n_in,
                              void* d_out, int out_size)
{
    const float* x     = (const float*)d_in[0];
    const int*   eidx  = (const int*)  d_in[1];
    const float* eattr = (const float*)d_in[2];
    const int*   batch = (const int*)  d_in[3];
    const float *We1 = (const float*)d_in[4],  *be1 = (const float*)d_in[5];
    const float *ro1 = (const float*)d_in[6],  *b1  = (const float*)d_in[7];
    const float *We2 = (const float*)d_in[8],  *be2 = (const float*)d_in[9];
    const float *ro2 = (const float*)d_in[10], *b2  = (const float*)d_in[11];
    const float *We3 = (const float*)d_in[12], *be3 = (const float*)d_in[13];
    const float *ro3 = (const float*)d_in[14], *b3  = (const float*)d_in[15];
    const float *W1  = (const float*)d_in[16], *c1  = (const float*)d_in[17];
    const float *W2  = (const float*)d_in[18], *c2  = (const float*)d_in[19];
    const float *W3  = (const float*)d_in[20], *c3  = (const float*)d_in[21];
    const float *W4  = (const float*)d_in[22], *c4  = (const float*)d_in[23];

    float *A2T, *A3T, *Z2p, *Z3p, *H1, *H2, *H3;
    cudaGetSymbolAddress((void**)&A2T, g_A2T);
    cudaGetSymbolAddress((void**)&A3T, g_A3T);
    cudaGetSymbolAddress((void**)&Z2p, g_Z2p);
    cudaGetSymbolAddress((void**)&Z3p, g_Z3p);
    cudaGetSymbolAddress((void**)&H1,  g_H1);
    cudaGetSymbolAddress((void**)&H2,  g_H2);
    cudaGetSymbolAddress((void**)&H3,  g_H3);

    cudaLaunchAttribute attr;
    attr.id = cudaLaunchAttributeProgrammaticStreamSerialization;
    attr.val.programmaticStreamSerializationAllowed = 1;

    auto mkcfg = [&](int gx, int gy, int nt) {
        cudaLaunchConfig_t cf{};
        cf.gridDim  = dim3((unsigned)gx, (unsigned)gy, 1);
        cf.blockDim = dim3((unsigned)nt, 1, 1);
        cf.dynamicSmemBytes = 0;
        cf.stream = 0;
        cf.attrs = &attr;
        cf.numAttrs = 1;
        return cf;
    };

    cudaLaunchConfig_t cf;

    // 1) layer-1 GEMM + fused relu -> H1 + A2T identity rows
    cf = mkcfg(16, 1, 128);
    cudaLaunchKernelEx(&cf, k_main1, x, eidx, eattr, We1, be1, ro1, b1, H1, A2T);

    // 2) M_j rows of A2T = P_j^T H1
    cf = mkcfg(16, 5, 256);
    cudaLaunchKernelEx(&cf, k_pgemm, (const float*)H1, K2, eidx, eattr, A2T);

    // 3) layer-2 GEMM: 4 col tiles x 150 slices (600 blocks, per-slice stores)
    cf = mkcfg(4, S2, 128);
    cudaLaunchKernelEx(&cf, k_main, (const float*)A2T, K2, O2, We2, be2, ro2, Z2p, 80);

    // 4) relu(sum_150 Z2p + b2) -> H2 + identity rows of A3T
    cf = mkcfg(8, 8, 128);
    cudaLaunchKernelEx(&cf, k_relu<S2>, (const float*)Z2p, b2, K3, A3T, H2);

    // 5) M_j rows of A3T = P_j^T H2
    cf = mkcfg(4, 5, 256);
    cudaLaunchKernelEx(&cf, k_pgemm, (const float*)H2, K3, eidx, eattr, A3T);

    // 6) layer-3 GEMM: 1 col tile x 94 slices
    cf = mkcfg(1, S3, 128);
    cudaLaunchKernelEx(&cf, k_main, (const float*)A3T, K3, O3, We3, be3, ro3, Z3p, 32);

    // 7) relu(sum_94 Z3p + b3) -> H3 (identity rows land in dead A3T space)
    cf = mkcfg(2, 8, 128);
    cudaLaunchKernelEx(&cf, k_relu<S3>, (const float*)Z3p, b3, O3, A3T, H3);

    // 8) head
    cf = mkcfg(NGRAPH, 1, 256);
    cudaLaunchKernelEx(&cf, k_head, (const float*)H3, batch,
                       W1, c1, W2, c2, W3, c3, W4, c4, (float*)d_out);
}

// round 17
// speedup vs baseline: 1.6037x; 1.6037x over previous
#include <cuda_runtime.h>
#include <cstdint>

#define NNODES 64
#define NEDGES 128
#define NGRAPH 4

typedef unsigned long long ull;

#define O1 2000
#define O2 500
#define O3 100
#define K2 2000
#define K3 500
#define S2 120      // layer-2 K slices (kChunk 100, 120*100 = 12000 exact)
#define S3 94       // layer-3 K slices (kChunk 32)

// ---------------- scratch ----------------
__device__ float g_A2T[6 * K2 * 64];
__device__ float g_A3T[6 * K3 * 64];
__device__ float g_Z2p[S2 * 64 * O2];
__device__ float g_Z3p[S3 * 64 * O3];
__device__ float g_H1 [64 * K2];
__device__ float g_H2 [64 * K3];
__device__ float g_H3 [64 * O3];

// ---------------- helpers ----------------
__device__ __forceinline__ void gdc_wait() {
    asm volatile("griddepcontrol.wait;" ::: "memory");
}
__device__ __forceinline__ void gdc_launch() {
    asm volatile("griddepcontrol.launch_dependents;" ::: "memory");
}
__device__ __forceinline__ ull dup2(float x) {
    ull r; asm("mov.b64 %0, {%1, %1};" : "=l"(r) : "f"(x)); return r;
}
__device__ __forceinline__ void fma2(ull &d, ull a, ull b) {
    asm("fma.rn.f32x2 %0, %1, %2, %3;" : "=l"(d) : "l"(a), "l"(b), "l"(d));
}
__device__ __forceinline__ float2 unpk(ull v) {
    float2 r; asm("mov.b64 {%0, %1}, %2;" : "=f"(r.x), "=f"(r.y) : "l"(v)); return r;
}
__device__ __forceinline__ void cpa16(void* dst, const void* src) {
    uint32_t d = (uint32_t)__cvta_generic_to_shared(dst);
    asm volatile("cp.async.cg.shared.global [%0], [%1], 16;\n" :: "r"(d), "l"(src));
}
__device__ __forceinline__ void cpa_commit() {
    asm volatile("cp.async.commit_group;\n" ::: "memory");
}
template<int N> __device__ __forceinline__ void cpa_wait() {
    asm volatile("cp.async.wait_group %0;\n" :: "n"(N) : "memory");
}

#define FMA_BLOCK \
    ull b0 = dup2(bL.x), b1 = dup2(bL.y), b2 = dup2(bL.z), b3 = dup2(bL.w); \
    ull b4 = dup2(bH.x), b5 = dup2(bH.y), b6 = dup2(bH.z), b7 = dup2(bH.w); \
    fma2(acc[0][0], a0, b0); fma2(acc[0][1], a0, b1); fma2(acc[0][2], a0, b2); fma2(acc[0][3], a0, b3); \
    fma2(acc[0][4], a0, b4); fma2(acc[0][5], a0, b5); fma2(acc[0][6], a0, b6); fma2(acc[0][7], a0, b7); \
    fma2(acc[1][0], a1, b0); fma2(acc[1][1], a1, b1); fma2(acc[1][2], a1, b2); fma2(acc[1][3], a1, b3); \
    fma2(acc[1][4], a1, b4); fma2(acc[1][5], a1, b5); fma2(acc[1][6], a1, b6); fma2(acc[1][7], a1, b7); \
    fma2(acc[2][0], a2, b0); fma2(acc[2][1], a2, b1); fma2(acc[2][2], a2, b2); fma2(acc[2][3], a2, b3); \
    fma2(acc[2][4], a2, b4); fma2(acc[2][5], a2, b5); fma2(acc[2][6], a2, b6); fma2(acc[2][7], a2, b7); \
    fma2(acc[3][0], a3, b0); fma2(acc[3][1], a3, b1); fma2(acc[3][2], a3, b2); fma2(acc[3][3], a3, b3); \
    fma2(acc[3][4], a3, b4); fma2(acc[3][5], a3, b5); fma2(acc[3][6], a3, b6); fma2(acc[3][7], a3, b7);

// ================= k_main1: layer-1 GEMM + FUSED bias/relu -> H1 + A2T identity rows =================
__global__ __launch_bounds__(128) void k_main1(
    const float* __restrict__ x, const int* __restrict__ eidx,
    const float* __restrict__ eattr,
    const float* __restrict__ We, const float* __restrict__ be,
    const float* __restrict__ root, const float* __restrict__ bias,
    float* __restrict__ H, float* __restrict__ A2T)
{
    __shared__ float sA[54 * 64];
    __shared__ float sB[54 * 128];

    gdc_wait();
    gdc_launch();
    const int t = threadIdx.x;
    const int c0 = blockIdx.x * 128;

    for (int i = t; i < 54 * 32; i += 128) {
        int r = i >> 5, c4 = (i & 31) * 4;
        int c = c0 + c4;
        float4* bd = (float4*)&sB[r * 128 + c4];
        if (c < O1) {
            const float* P;
            if      (r < 36) P = We   + (size_t)r * O1;
            else if (r < 45) P = be   + (size_t)(r - 36) * O1;
            else             P = root + (size_t)(r - 45) * O1;
            cpa16(bd, P + c);
        } else *bd = make_float4(0,0,0,0);
    }
    cpa_commit();

    for (int i = t; i < 54 * 64; i += 128) sA[i] = 0.f;
    __syncthreads();
    if (t < NEDGES) {
        int s = eidx[t], d = eidx[NEDGES + t];
        float xs[9];
        #pragma unroll
        for (int i = 0; i < 9; i++) xs[i] = x[s * 9 + i];
        #pragma unroll
        for (int j = 0; j < 4; j++) {
            float w = eattr[t * 4 + j];
            #pragma unroll
            for (int i = 0; i < 9; i++)
                atomicAdd(&sA[(j * 9 + i) * 64 + d], w * xs[i]);
        }
        #pragma unroll
        for (int i = 0; i < 9; i++)
            atomicAdd(&sA[(36 + i) * 64 + d], xs[i]);
    }
    if (t < 64) {
        #pragma unroll
        for (int i = 0; i < 9; i++)
            sA[(45 + i) * 64 + t] = x[t * 9 + i];
    }
    cpa_wait<0>();
    __syncthreads();

    const int tx = t & 15, ty = t >> 4;
    ull acc[4][8];
    #pragma unroll
    for (int r = 0; r < 4; r++)
        #pragma unroll
        for (int j = 0; j < 8; j++) acc[r][j] = 0ull;

    for (int r = 0; r < 54; r++) {
        const float* as = &sA[r * 64 + 8 * ty];
        ull a0 = *(const ull*)(as);
        ull a1 = *(const ull*)(as + 2);
        ull a2 = *(const ull*)(as + 4);
        ull a3 = *(const ull*)(as + 6);
        float4 bL = *(const float4*)&sB[r * 128 + 4 * tx];
        float4 bH = *(const float4*)&sB[r * 128 + 64 + 4 * tx];
        FMA_BLOCK
    }

    const int cL = c0 + 4 * tx;
    const int cH = c0 + 64 + 4 * tx;
    const bool hv = (cH + 3 < O1);
    float4 bL4 = *(const float4*)&bias[cL];
    float4 bH4 = hv ? *(const float4*)&bias[cH] : make_float4(0,0,0,0);

    float rr[8][8];
    #pragma unroll
    for (int rp = 0; rp < 4; rp++) {
        #pragma unroll
        for (int jc = 0; jc < 4; jc++) {
            float2 vL = unpk(acc[rp][jc]);
            float2 vH = unpk(acc[rp][4 + jc]);
            float bl = (&bL4.x)[jc], bh = (&bH4.x)[jc];
            rr[2 * rp][jc]         = fmaxf(vL.x + bl, 0.f);
            rr[2 * rp + 1][jc]     = fmaxf(vL.y + bl, 0.f);
            rr[2 * rp][4 + jc]     = fmaxf(vH.x + bh, 0.f);
            rr[2 * rp + 1][4 + jc] = fmaxf(vH.y + bh, 0.f);
        }
    }
    #pragma unroll
    for (int lr = 0; lr < 8; lr++) {
        int m = 8 * ty + lr;
        *(float4*)&H[(size_t)m * K2 + cL] = make_float4(rr[lr][0], rr[lr][1], rr[lr][2], rr[lr][3]);
        if (hv)
            *(float4*)&H[(size_t)m * K2 + cH] = make_float4(rr[lr][4], rr[lr][5], rr[lr][6], rr[lr][7]);
    }
    #pragma unroll
    for (int jc = 0; jc < 4; jc++) {
        {
            int k = cL + jc;
            float* dst = A2T + (size_t)(5 * K2 + k) * 64 + 8 * ty;
            *(float4*)dst       = make_float4(rr[0][jc], rr[1][jc], rr[2][jc], rr[3][jc]);
            *(float4*)(dst + 4) = make_float4(rr[4][jc], rr[5][jc], rr[6][jc], rr[7][jc]);
        }
        if (hv) {
            int k = cH + jc;
            float* dst = A2T + (size_t)(5 * K2 + k) * 64 + 8 * ty;
            *(float4*)dst       = make_float4(rr[0][4+jc], rr[1][4+jc], rr[2][4+jc], rr[3][4+jc]);
            *(float4*)(dst + 4) = make_float4(rr[4][4+jc], rr[5][4+jc], rr[6][4+jc], rr[7][4+jc]);
        }
    }
}

// ================= k_relu<G>: PARALLEL reducer =================
// grid (ceil(Klen/64), 64 nodes), 128 threads. Thread (sub = t>>4) sums slices
// g = sub, sub+8, ...; smem tree-reduce 8->1; bias+relu; write H + identity row.
template<int G>
__global__ __launch_bounds__(128) void k_relu(
    const float* __restrict__ Z, const float* __restrict__ bias, int Klen,
    float* __restrict__ AoutT, float* __restrict__ Hout)
{
    __shared__ float red[8][68];

    gdc_wait();
    gdc_launch();

    const int t   = threadIdx.x;
    const int k0  = blockIdx.x * 64;
    const int n   = blockIdx.y;
    const int k4  = (t & 15) << 2;
    const int sub = t >> 4;
    const int kk  = k0 + k4;

    float4 v = make_float4(0.f, 0.f, 0.f, 0.f);
    if (kk < Klen) {
        const float* base = Z + (size_t)n * Klen + kk;
        for (int g = sub; g < G; g += 8) {
            float4 p = *(const float4*)(base + (size_t)g * 64 * Klen);
            v.x += p.x; v.y += p.y; v.z += p.z; v.w += p.w;
        }
    }
    *(float4*)&red[sub][k4] = v;
    __syncthreads();

    if (t < 16) {
        const int kq = k0 + t * 4;
        if (kq < Klen) {
            float4 a = *(const float4*)&bias[kq];
            #pragma unroll
            for (int s = 0; s < 8; s++) {
                float4 p = *(const float4*)&red[s][t * 4];
                a.x += p.x; a.y += p.y; a.z += p.z; a.w += p.w;
            }
            a.x = fmaxf(a.x, 0.f); a.y = fmaxf(a.y, 0.f);
            a.z = fmaxf(a.z, 0.f); a.w = fmaxf(a.w, 0.f);
            *(float4*)&Hout[(size_t)n * Klen + kq] = a;
            *(float4*)&red[0][t * 4] = a;
        }
    }
    __syncthreads();

    if (t < 64) {
        const int kq = k0 + t;
        if (kq < Klen)
            AoutT[(size_t)(5 * (size_t)Klen + kq) * 64 + n] = red[0][t];
    }
}

// ================= k_pgemm: M_j rows of A'' = P_j^T H =================
__global__ __launch_bounds__(256) void k_pgemm(
    const float* __restrict__ H, int Klen,
    const int* __restrict__ eidx, const float* __restrict__ eattr,
    float* __restrict__ AoutT)
{
    __shared__ float sh[64 * 128];
    __shared__ float sP[64 * 64];

    gdc_wait();
    gdc_launch();

    const int t  = threadIdx.x;
    const int k0 = blockIdx.x * 128;
    const int j  = blockIdx.y;

    for (int i = t; i < 2048; i += 256) {
        int n = i >> 5, k4 = (i & 31) << 2;
        int kk = k0 + k4;
        if (kk < Klen) cpa16(&sh[n * 128 + k4], &H[(size_t)n * Klen + kk]);
        else           *(float4*)&sh[n * 128 + k4] = make_float4(0,0,0,0);
    }
    cpa_commit();
    for (int i = t; i < 4096; i += 256) sP[i] = 0.f;
    __syncthreads();
    if (t < NEDGES) {
        int s = eidx[t], d = eidx[NEDGES + t];
        float w = (j < 4) ? eattr[t * 4 + j] : 1.f;
        atomicAdd(&sP[s * 64 + d], w);
    }
    cpa_wait<0>();
    __syncthreads();

    const int tx = t & 31;
    const int ty = t >> 5;
    ull acc[4][4];
    #pragma unroll
    for (int r = 0; r < 4; r++)
        #pragma unroll
        for (int c = 0; c < 4; c++) acc[r][c] = 0ull;

    for (int n = 0; n < 64; n++) {
        const float* as = &sP[n * 64 + 8 * ty];
        ull a0 = *(const ull*)(as);
        ull a1 = *(const ull*)(as + 2);
        ull a2 = *(const ull*)(as + 4);
        ull a3 = *(const ull*)(as + 6);
        float4 b = *(const float4*)&sh[n * 128 + 4 * tx];
        ull b0 = dup2(b.x), b1 = dup2(b.y), b2 = dup2(b.z), b3 = dup2(b.w);
        fma2(acc[0][0], a0, b0); fma2(acc[0][1], a0, b1); fma2(acc[0][2], a0, b2); fma2(acc[0][3], a0, b3);
        fma2(acc[1][0], a1, b0); fma2(acc[1][1], a1, b1); fma2(acc[1][2], a1, b2); fma2(acc[1][3], a1, b3);
        fma2(acc[2][0], a2, b0); fma2(acc[2][1], a2, b1); fma2(acc[2][2], a2, b2); fma2(acc[2][3], a2, b3);
        fma2(acc[3][0], a3, b0); fma2(acc[3][1], a3, b1); fma2(acc[3][2], a3, b2); fma2(acc[3][3], a3, b3);
    }

    #pragma unroll
    for (int jc = 0; jc < 4; jc++) {
        int k = k0 + 4 * tx + jc;
        if (k < Klen) {
            size_t row = (size_t)((size_t)j * Klen + k) * 64;
            float2 p0 = unpk(acc[0][jc]), p1 = unpk(acc[1][jc]);
            float2 p2 = unpk(acc[2][jc]), p3 = unpk(acc[3][jc]);
            *(float4*)&AoutT[row + 8 * ty]     = make_float4(p0.x, p0.y, p1.x, p1.y);
            *(float4*)&AoutT[row + 8 * ty + 4] = make_float4(p2.x, p2.y, p3.x, p3.y);
        }
    }
}

// ================= k_main: split-K GEMM, plain per-slice store epilogue =================
__global__ __launch_bounds__(128) void k_main(
    const float* __restrict__ AT, int Kj, int O,
    const float* __restrict__ We, const float* __restrict__ be,
    const float* __restrict__ root, float* __restrict__ Zp, int kChunk)
{
    __shared__ float As[3][16][68];
    __shared__ float Bs[3][16][128];

    gdc_wait();
    gdc_launch();

    const int t    = threadIdx.x;
    const int Ktot = 6 * Kj;
    const int c0   = blockIdx.x * 128;
    const int k0   = blockIdx.y * kChunk;
    const int kend = min(k0 + kChunk, Ktot);
    const int nsteps = (kend - k0 + 15) >> 4;
    float* Z = Zp + (size_t)blockIdx.y * 64 * O;

    const int kkB   = t >> 3;
    const int cbase = (t & 7) * 16;
    const float4 z4 = make_float4(0.f, 0.f, 0.f, 0.f);

    auto stage = [&](int s, int buf) {
        const int kt = k0 + s * 16;
        const int kb = kend - kt;
        #pragma unroll
        for (int i = 0; i < 4; i++) {
            int cl = cbase + 4 * i;
            int c  = c0 + cl;
            float4* bd = (float4*)&Bs[buf][kkB][cl];
            if (kkB < kb && c < O) {
                int rr = kt + kkB;
                const float* P;
                if      (rr < 4 * Kj) P = We   + (size_t)rr * O;
                else if (rr < 5 * Kj) P = be   + (size_t)(rr - 4 * Kj) * O;
                else                  P = root + (size_t)(rr - 5 * Kj) * O;
                cpa16(bd, P + c);
            } else *bd = z4;
        }
        #pragma unroll
        for (int i = 0; i < 2; i++) {
            int q  = t + 128 * i;
            int kk = q >> 4, m4 = (q & 15) * 4;
            float4* ad = (float4*)&As[buf][kk][m4];
            if (kk < kb) cpa16(ad, AT + (size_t)(kt + kk) * 64 + m4);
            else         *ad = z4;
        }
        cpa_commit();
    };

    stage(0, 0);
    if (nsteps > 1) stage(1, 1);

    const int tx = t & 15, ty = t >> 4;
    ull acc[4][8];
    #pragma unroll
    for (int r = 0; r < 4; r++)
        #pragma unroll
        for (int j = 0; j < 8; j++) acc[r][j] = 0ull;

    for (int s = 0; s < nsteps; s++) {
        const int buf = s % 3;
        if (s + 2 < nsteps)      { stage(s + 2, (s + 2) % 3); cpa_wait<2>(); }
        else if (s + 1 < nsteps) { cpa_wait<1>(); }
        else                     { cpa_wait<0>(); }
        __syncthreads();

        #pragma unroll
        for (int kk = 0; kk < 16; kk++) {
            const float* as = &As[buf][kk][8 * ty];
            ull a0 = *(const ull*)(as);
            ull a1 = *(const ull*)(as + 2);
            ull a2 = *(const ull*)(as + 4);
            ull a3 = *(const ull*)(as + 6);
            float4 bL = *(const float4*)&Bs[buf][kk][4 * tx];
            float4 bH = *(const float4*)&Bs[buf][kk][64 + 4 * tx];
            FMA_BLOCK
        }
        __syncthreads();
    }

    const int cL = c0 + 4 * tx;
    const int cH = c0 + 64 + 4 * tx;
    #pragma unroll
    for (int rp = 0; rp < 4; rp++) {
        int m = 8 * ty + 2 * rp;
        float2 v[8];
        #pragma unroll
        for (int j = 0; j < 8; j++) v[j] = unpk(acc[rp][j]);
        if (cL < O) {
            *(float4*)&Z[(size_t)m       * O + cL] = make_float4(v[0].x, v[1].x, v[2].x, v[3].x);
            *(float4*)&Z[(size_t)(m + 1) * O + cL] = make_float4(v[0].y, v[1].y, v[2].y, v[3].y);
        }
        if (cH + 3 < O) {
            *(float4*)&Z[(size_t)m       * O + cH] = make_float4(v[4].x, v[5].x, v[6].x, v[7].x);
            *(float4*)&Z[(size_t)(m + 1) * O + cH] = make_float4(v[4].y, v[5].y, v[6].y, v[7].y);
        }
    }
}

// ================= fused FCN head (reads dense relu'd H3) =================
__global__ __launch_bounds__(256) void k_head(
    const float* __restrict__ H3, const int* __restrict__ batch,
    const float* __restrict__ W1, const float* __restrict__ c1,
    const float* __restrict__ W2, const float* __restrict__ c2,
    const float* __restrict__ W3, const float* __restrict__ c3,
    const float* __restrict__ W4, const float* __restrict__ c4,
    float* __restrict__ out)
{
    __shared__ float gS[100];
    __shared__ float s1[1000];
    __shared__ float part[200];
    __shared__ float s2[100];
    __shared__ float s3[50];
    __shared__ int   sb[NNODES];

    gdc_wait();

    const int g = blockIdx.x;
    const int t = threadIdx.x;

    if (t < NNODES) sb[t] = batch[t];
    __syncthreads();

    if (t < 100) {
        float a = 0.f;
        for (int n = 0; n < NNODES; n++)
            if (sb[n] == g) a += H3[n * 100 + t];
        gS[t] = a;
    }
    __syncthreads();

    for (int f = t; f < 1000; f += 256) {
        float a = c1[f];
        for (int kq = 0; kq < 100; kq++) a += gS[kq] * W1[kq * 1000 + f];
        s1[f] = fmaxf(a, 0.f);
    }
    __syncthreads();

    if (t < 200) {
        int f = t % 100, hh = t / 100;
        float a = 0.f;
        int kq0 = hh * 500;
        for (int kq = kq0; kq < kq0 + 500; kq++) a += s1[kq] * W2[kq * 100 + f];
        part[t] = a;
    }
    __syncthreads();
    if (t < 100) s2[t] = fmaxf(part[t] + part[100 + t] + c2[t], 0.f);
    __syncthreads();

    if (t < 50) {
        float a = c3[t];
        for (int kq = 0; kq < 100; kq++) a += s2[kq] * W3[kq * 50 + t];
        s3[t] = fmaxf(a, 0.f);
    }
    __syncthreads();

    if (t < 32) {
        float a = (t < 50) ? s3[t] * W4[t] : 0.f;
        if (t + 32 < 50) a += s3[t + 32] * W4[t + 32];
        #pragma unroll
        for (int o = 16; o > 0; o >>= 1)
            a += __shfl_xor_sync(0xffffffffu, a, o);
        if (t == 0) out[g] = a + c4[0];
    }
}

// ---------------- launch (8 PDL-chained kernels, no global atomics) ----------------
extern "C" void kernel_launch(void* const* d_in, const int* in_sizes, int n_in,
                              void* d_out, int out_size)
{
    const float* x     = (const float*)d_in[0];
    const int*   eidx  = (const int*)  d_in[1];
    const float* eattr = (const float*)d_in[2];
    const int*   batch = (const int*)  d_in[3];
    const float *We1 = (const float*)d_in[4],  *be1 = (const float*)d_in[5];
    const float *ro1 = (const float*)d_in[6],  *b1  = (const float*)d_in[7];
    const float *We2 = (const float*)d_in[8],  *be2 = (const float*)d_in[9];
    const float *ro2 = (const float*)d_in[10], *b2  = (const float*)d_in[11];
    const float *We3 = (const float*)d_in[12], *be3 = (const float*)d_in[13];
    const float *ro3 = (const float*)d_in[14], *b3  = (const float*)d_in[15];
    const float *W1  = (const float*)d_in[16], *c1  = (const float*)d_in[17];
    const float *W2  = (const float*)d_in[18], *c2  = (const float*)d_in[19];
    const float *W3  = (const float*)d_in[20], *c3  = (const float*)d_in[21];
    const float *W4  = (const float*)d_in[22], *c4  = (const float*)d_in[23];

    float *A2T, *A3T, *Z2p, *Z3p, *H1, *H2, *H3;
    cudaGetSymbolAddress((void**)&A2T, g_A2T);
    cudaGetSymbolAddress((void**)&A3T, g_A3T);
    cudaGetSymbolAddress((void**)&Z2p, g_Z2p);
    cudaGetSymbolAddress((void**)&Z3p, g_Z3p);
    cudaGetSymbolAddress((void**)&H1,  g_H1);
    cudaGetSymbolAddress((void**)&H2,  g_H2);
    cudaGetSymbolAddress((void**)&H3,  g_H3);

    cudaLaunchAttribute attr;
    attr.id = cudaLaunchAttributeProgrammaticStreamSerialization;
    attr.val.programmaticStreamSerializationAllowed = 1;

    auto mkcfg = [&](int gx, int gy, int nt) {
        cudaLaunchConfig_t cf{};
        cf.gridDim  = dim3((unsigned)gx, (unsigned)gy, 1);
        cf.blockDim = dim3((unsigned)nt, 1, 1);
        cf.dynamicSmemBytes = 0;
        cf.stream = 0;
        cf.attrs = &attr;
        cf.numAttrs = 1;
        return cf;
    };

    cudaLaunchConfig_t cf;

    // 1) layer-1 GEMM + fused relu -> H1 + A2T identity rows
    cf = mkcfg(16, 1, 128);
    cudaLaunchKernelEx(&cf, k_main1, x, eidx, eattr, We1, be1, ro1, b1, H1, A2T);

    // 2) M_j rows of A2T = P_j^T H1
    cf = mkcfg(16, 5, 256);
    cudaLaunchKernelEx(&cf, k_pgemm, (const float*)H1, K2, eidx, eattr, A2T);

    // 3) layer-2 GEMM: 4 col tiles x 120 slices (480 blocks, single wave)
    cf = mkcfg(4, S2, 128);
    cudaLaunchKernelEx(&cf, k_main, (const float*)A2T, K2, O2, We2, be2, ro2, Z2p, 100);

    // 4) parallel reduce: relu(sum_120 Z2p + b2) -> H2 + A3T identity (8 x 64 blocks)
    cf = mkcfg(8, 64, 128);
    cudaLaunchKernelEx(&cf, k_relu<S2>, (const float*)Z2p, b2, K3, A3T, H2);

    // 5) M_j rows of A3T = P_j^T H2
    cf = mkcfg(4, 5, 256);
    cudaLaunchKernelEx(&cf, k_pgemm, (const float*)H2, K3, eidx, eattr, A3T);

    // 6) layer-3 GEMM: 1 col tile x 94 slices
    cf = mkcfg(1, S3, 128);
    cudaLaunchKernelEx(&cf, k_main, (const float*)A3T, K3, O3, We3, be3, ro3, Z3p, 32);

    // 7) parallel reduce: relu(sum_94 Z3p + b3) -> H3 (identity into dead A3T)
    cf = mkcfg(2, 64, 128);
    cudaLaunchKernelEx(&cf, k_relu<S3>, (const float*)Z3p, b3, O3, A3T, H3);

    // 8) head
    cf = mkcfg(NGRAPH, 1, 256);
    cudaLaunchKernelEx(&cf, k_head, (const float*)H3, batch,
                       W1, c1, W2, c2, W3, c3, W4, c4, (float*)d_out);
}